// round 13
// baseline (speedup 1.0000x reference)
#include <cuda_runtime.h>
#include <cuda_bf16.h>
#include <stdint.h>

// Problem dims (fixed by the dataset)
#define NBATCH 4
#define NROWS  8192
#define DMEM   128
#define NTILES 64
#define TILEB  32768        // 128 rows * 128 bf16 * 2B
#define THRESH 0.65f
#define HITCAP 65536
#define SIMGRID (NBATCH * 32 * 8)   // 1024 CTAs

// Scratch (device globals are the sanctioned scratch mechanism)
__device__ __align__(16) __nv_bfloat16 g_proj[(size_t)NBATCH * NROWS * DMEM]; // 8 MB normalized proj
__device__ uint2 g_hits[HITCAP];
__device__ unsigned g_hitcnt;
__device__ unsigned g_done;

// ---------------------------------------------------------------------------
// helpers
// ---------------------------------------------------------------------------
__device__ __forceinline__ uint32_t su32(const void* p) {
    uint32_t a;
    asm("{ .reg .u64 t; cvta.to.shared.u64 t, %1; cvt.u32.u64 %0, t; }" : "=r"(a) : "l"(p));
    return a;
}

#define LDMATRIX_X4(r0, r1, r2, r3, addr) \
    asm volatile("ldmatrix.sync.aligned.m8n8.x4.shared.b16 {%0,%1,%2,%3}, [%4];" \
                 : "=r"(r0), "=r"(r1), "=r"(r2), "=r"(r3) : "r"(addr))

#define MMA_BF16(d, a, b0, b1) \
    asm volatile("mma.sync.aligned.m16n8k16.row.col.f32.bf16.bf16.f32 " \
                 "{%0,%1,%2,%3}, {%4,%5,%6,%7}, {%8,%9}, {%0,%1,%2,%3};" \
                 : "+f"((d)[0]), "+f"((d)[1]), "+f"((d)[2]), "+f"((d)[3]) \
                 : "r"((a)[0]), "r"((a)[1]), "r"((a)[2]), "r"((a)[3]), "r"(b0), "r"(b1))

// bf16 128x128 tile (32KB, 256B rows, 16 chunks/row, c^(r&7) swizzle). 256 thr.
__device__ __forceinline__ void copy_tile16(uint32_t dst, const __nv_bfloat16* src, int tid) {
    #pragma unroll
    for (int k = 0; k < 8; k++) {
        int idx = tid + k * 256;
        int r = idx >> 4, c = idx & 15;
        uint32_t doff = (uint32_t)(r * 256 + ((c ^ (r & 7)) << 4));
        asm volatile("cp.async.cg.shared.global [%0], [%1], 16;"
                     :: "r"(dst + doff), "l"((const char*)src + (size_t)idx * 16) : "memory");
    }
}

// fp32 128x128 tile -> bf16 swizzled smem (ld+cvt+st). 256 threads.
__device__ __forceinline__ void conv_tile(unsigned char* dsm_base, const float* src, int tid) {
    #pragma unroll
    for (int k = 0; k < 8; k++) {
        int idx = tid + k * 256;
        int r = idx >> 4, c = idx & 15;
        const float4* s = reinterpret_cast<const float4*>(src + (size_t)r * DMEM + c * 8);
        float4 f0 = s[0], f1 = s[1];
        __nv_bfloat162 h0 = __floats2bfloat162_rn(f0.x, f0.y);
        __nv_bfloat162 h1 = __floats2bfloat162_rn(f0.z, f0.w);
        __nv_bfloat162 h2 = __floats2bfloat162_rn(f1.x, f1.y);
        __nv_bfloat162 h3 = __floats2bfloat162_rn(f1.z, f1.w);
        *reinterpret_cast<uint4*>(dsm_base + r * 256 + ((c ^ (r & 7)) << 4)) =
            make_uint4(*(uint32_t*)&h0, *(uint32_t*)&h1, *(uint32_t*)&h2, *(uint32_t*)&h3);
    }
}

// Load this warp's resident A fragments (m32 x k128) from swizzled smA.
__device__ __forceinline__ void load_afrags(uint32_t a[2][8][4], uint32_t smA, int wm, int l) {
    #pragma unroll
    for (int m = 0; m < 2; m++)
        #pragma unroll
        for (int k = 0; k < 8; k++) {
            int r = wm * 32 + m * 16 + (l & 15);
            int chunk = k * 2 + ((l >> 4) & 1);
            uint32_t addr = smA + r * 256 + ((chunk ^ (r & 7)) << 4);
            LDMATRIX_X4(a[m][k][0], a[m][k][1], a[m][k][2], a[m][k][3], addr);
        }
}

// ---------------------------------------------------------------------------
// Stage 1 (R11-proven, 15.0us): proj = normalize(X @ W^T + b) -> bf16,
// via bf16 mma. W converted inline; also writes out = X. 256 CTAs x 256 thr.
// Resets g_hitcnt / g_done for this run.
// ---------------------------------------------------------------------------
__global__ void __launch_bounds__(256) proj_kernel(const float* __restrict__ X,
                                                   const float* __restrict__ W,
                                                   const float* __restrict__ Bv,
                                                   float* __restrict__ out) {
    extern __shared__ unsigned char dsm[];
    uint32_t smX = su32(dsm);            // 32 KB (swizzled)
    uint32_t smW = smX + TILEB;          // 32 KB (swizzled)
    float* bs = (float*)(dsm + 2 * TILEB);

    int tid = threadIdx.x, w = tid >> 5, l = tid & 31;
    int r0 = blockIdx.x * 128;

    if (blockIdx.x == 0 && tid == 0) { g_hitcnt = 0u; g_done = 0u; }
    if (tid < 128) bs[tid] = Bv[tid];

    conv_tile(dsm + TILEB, W, tid);                   // W fp32 -> bf16 smem

    // X fp32 -> bf16 into swizzled smem; forward fp32 to out (out = X).
    #pragma unroll
    for (int k = 0; k < 8; k++) {
        int idx = tid + k * 256;
        int r = idx >> 4, c = idx & 15;
        size_t gbase = ((size_t)(r0 + r) * DMEM + c * 8);
        float4 f0 = reinterpret_cast<const float4*>(X + gbase)[0];
        float4 f1 = reinterpret_cast<const float4*>(X + gbase)[1];
        reinterpret_cast<float4*>(out + gbase)[0] = f0;
        reinterpret_cast<float4*>(out + gbase)[1] = f1;
        __nv_bfloat162 h0 = __floats2bfloat162_rn(f0.x, f0.y);
        __nv_bfloat162 h1 = __floats2bfloat162_rn(f0.z, f0.w);
        __nv_bfloat162 h2 = __floats2bfloat162_rn(f1.x, f1.y);
        __nv_bfloat162 h3 = __floats2bfloat162_rn(f1.z, f1.w);
        *reinterpret_cast<uint4*>(dsm + r * 256 + ((c ^ (r & 7)) << 4)) =
            make_uint4(*(uint32_t*)&h0, *(uint32_t*)&h1, *(uint32_t*)&h2, *(uint32_t*)&h3);
    }
    __syncthreads();

    float acc[16][4];
    #pragma unroll
    for (int f = 0; f < 16; f++)
        #pragma unroll
        for (int p = 0; p < 4; p++) acc[f][p] = 0.f;

    #pragma unroll
    for (int k = 0; k < 8; k++) {
        uint32_t a[4];
        {
            int r = w * 16 + (l & 15);
            int chunk = k * 2 + ((l >> 4) & 1);
            uint32_t addr = smX + r * 256 + ((chunk ^ (r & 7)) << 4);
            LDMATRIX_X4(a[0], a[1], a[2], a[3], addr);
        }
        #pragma unroll
        for (int nf = 0; nf < 8; nf++) {
            int nn = nf * 16 + (l & 7) + ((l & 16) ? 8 : 0);
            int chunk = k * 2 + ((l >> 3) & 1);
            uint32_t addr = smW + nn * 256 + ((chunk ^ (nn & 7)) << 4);
            uint32_t b0, b1, b2, b3;
            LDMATRIX_X4(b0, b1, b2, b3, addr);
            MMA_BF16(acc[nf * 2],     a, b0, b1);
            MMA_BF16(acc[nf * 2 + 1], a, b2, b3);
        }
    }

    // bias + row sums of squares (rows l/4 and l/4+8 of this warp's m16)
    float slo = 0.f, shi = 0.f;
    #pragma unroll
    for (int f = 0; f < 16; f++) {
        int c0 = f * 8 + 2 * (l & 3);
        float b0 = bs[c0], b1 = bs[c0 + 1];
        acc[f][0] += b0; acc[f][1] += b1;
        acc[f][2] += b0; acc[f][3] += b1;
        slo += acc[f][0] * acc[f][0] + acc[f][1] * acc[f][1];
        shi += acc[f][2] * acc[f][2] + acc[f][3] * acc[f][3];
    }
    slo += __shfl_xor_sync(0xffffffffu, slo, 1);
    slo += __shfl_xor_sync(0xffffffffu, slo, 2);
    shi += __shfl_xor_sync(0xffffffffu, shi, 1);
    shi += __shfl_xor_sync(0xffffffffu, shi, 2);
    float rlo = rsqrtf(fmaxf(slo, 1e-24f));
    float rhi = rsqrtf(fmaxf(shi, 1e-24f));

    int rowlo = r0 + w * 16 + (l >> 2);
    #pragma unroll
    for (int f = 0; f < 16; f++) {
        int c0 = f * 8 + 2 * (l & 3);
        __nv_bfloat162 hlo = __floats2bfloat162_rn(acc[f][0] * rlo, acc[f][1] * rlo);
        __nv_bfloat162 hhi = __floats2bfloat162_rn(acc[f][2] * rhi, acc[f][3] * rhi);
        *reinterpret_cast<uint32_t*>(g_proj + (size_t)rowlo * DMEM + c0)       = *(uint32_t*)&hlo;
        *reinterpret_cast<uint32_t*>(g_proj + (size_t)(rowlo + 8) * DMEM + c0) = *(uint32_t*)&hhi;
    }
}

// ---------------------------------------------------------------------------
// Stage 2: upper-triangular sim tiles (jt >= it) via bf16 mma.
// 1024 CTAs x 8-9 tiles (measured-optimal granularity). Rare hits append
// (i,j) [+ symmetric partner] to a global list. The LAST CTA to finish
// (done-counter) applies the hit list + scaling inline -> no fin launch.
// ---------------------------------------------------------------------------
__global__ void __launch_bounds__(256, 2) sim_kernel(const float* __restrict__ X,
                                                     float* __restrict__ out) {
    extern __shared__ unsigned char dsm[];
    __shared__ int s_last;
    uint32_t smA  = su32(dsm);
    uint32_t smB0 = smA + TILEB;
    uint32_t smB1 = smA + 2 * TILEB;

    int tid = threadIdx.x, wid = tid >> 5, l = tid & 31;
    int wm = wid >> 1, wn = wid & 1;

    int bid = blockIdx.x;
    int batch = bid >> 8;
    int p     = (bid >> 3) & 31;
    int q     = bid & 7;
    int n0    = NTILES - p;                 // tiles in row p
    int t0 = (q * 65) >> 3, t1 = ((q + 1) * 65) >> 3;

    const __nv_bfloat16* pb = g_proj + (size_t)batch * NROWS * DMEM;
    int bi = batch * NROWS;                 // global row offset for this batch

    #define JOF(t) (((t) < n0) ? (p + (t)) : ((63 - p) + ((t) - n0)))
    #define IOF(t) (((t) < n0) ? p : (63 - p))

    int cur_i = IOF(t0);
    copy_tile16(smA, pb + (size_t)cur_i * 128 * DMEM, tid);
    copy_tile16(smB0, pb + (size_t)JOF(t0) * 128 * DMEM, tid);
    asm volatile("cp.async.commit_group;" ::: "memory");
    if (t0 + 1 < t1)
        copy_tile16(smB1, pb + (size_t)JOF(t0 + 1) * 128 * DMEM, tid);
    asm volatile("cp.async.commit_group;" ::: "memory");
    asm volatile("cp.async.wait_group 1;" ::: "memory");
    __syncthreads();

    uint32_t a[2][8][4];
    load_afrags(a, smA, wm, l);

    for (int t = t0; t < t1; t++) {
        if (IOF(t) != cur_i) {             // row crossing (only 1-in-8 CTAs)
            cur_i = IOF(t);
            __syncthreads();
            copy_tile16(smA, pb + (size_t)cur_i * 128 * DMEM, tid);
            asm volatile("cp.async.commit_group;" ::: "memory");
            asm volatile("cp.async.wait_group 0;" ::: "memory");
            __syncthreads();
            load_afrags(a, smA, wm, l);
        }
        int it = cur_i, jt = JOF(t);
        uint32_t smB = ((t - t0) & 1) ? smB1 : smB0;

        #pragma unroll 1
        for (int g = 0; g < 4; g++) {
            int n0c = wn * 64 + g * 16;
            float d[2][2][4];
            #pragma unroll
            for (int m = 0; m < 2; m++)
                #pragma unroll
                for (int h = 0; h < 2; h++)
                    #pragma unroll
                    for (int pp = 0; pp < 4; pp++) d[m][h][pp] = 0.f;

            #pragma unroll
            for (int k = 0; k < 8; k++) {
                int nn = n0c + (l & 7) + ((l & 16) ? 8 : 0);
                int chunk = k * 2 + ((l >> 3) & 1);
                uint32_t addr = smB + nn * 256 + ((chunk ^ (nn & 7)) << 4);
                uint32_t b0, b1, b2, b3;
                LDMATRIX_X4(b0, b1, b2, b3, addr);
                #pragma unroll
                for (int m = 0; m < 2; m++) {
                    MMA_BF16(d[m][0], a[m][k], b0, b1);
                    MMA_BF16(d[m][1], a[m][k], b2, b3);
                }
            }

            float vmax = d[0][0][0];
            #pragma unroll
            for (int m = 0; m < 2; m++)
                #pragma unroll
                for (int h = 0; h < 2; h++)
                    #pragma unroll
                    for (int pp = 0; pp < 4; pp++) vmax = fmaxf(vmax, d[m][h][pp]);
            unsigned warp_any = __ballot_sync(0xffffffffu, vmax > THRESH);

            if (warp_any) {   // rare: diagonal tile self-sim, or a true hit
                bool diag = (it == jt);
                #pragma unroll
                for (int m = 0; m < 2; m++)
                    #pragma unroll
                    for (int h = 0; h < 2; h++)
                        #pragma unroll
                        for (int pp = 0; pp < 4; pp++) {
                            if (d[m][h][pp] > THRESH) {
                                int ib = bi + it * 128 + wm * 32 + m * 16 + (l >> 2) + ((pp & 2) ? 8 : 0);
                                int jb = bi + jt * 128 + n0c + h * 8 + 2 * (l & 3) + (pp & 1);
                                if (ib != jb) {
                                    unsigned idx = atomicAdd(&g_hitcnt, diag ? 1u : 2u);
                                    if (idx < HITCAP)
                                        g_hits[idx] = make_uint2((unsigned)ib, (unsigned)jb);
                                    if (!diag && idx + 1 < HITCAP)
                                        g_hits[idx + 1] = make_uint2((unsigned)jb, (unsigned)ib);
                                }
                            }
                        }
            }
        }

        __syncthreads();
        if (t + 2 < t1)
            copy_tile16(smB, pb + (size_t)JOF(t + 2) * 128 * DMEM, tid);
        asm volatile("cp.async.commit_group;" ::: "memory");
        asm volatile("cp.async.wait_group 1;" ::: "memory");
        __syncthreads();
    }
    #undef JOF
    #undef IOF

    // --- tail: last CTA to finish applies the (tiny) hit list + scaling ---
    if (tid == 0) {
        __threadfence();                              // publish this CTA's hits
        unsigned d = atomicAdd(&g_done, 1u);
        s_last = (d == SIMGRID - 1u) ? 1 : 0;
    }
    __syncthreads();
    if (s_last) {
        __threadfence();                              // acquire all CTAs' hits
        unsigned nh = g_hitcnt;
        if (nh > HITCAP) nh = HITCAP;
        // Pass 1: out[i] += X[j], in list order (deterministic fp order).
        for (unsigned h = 0; h < nh; h++) {
            unsigned row = g_hits[h].x, j = g_hits[h].y;
            if (tid < DMEM)
                out[(size_t)row * DMEM + tid] += X[(size_t)j * DMEM + tid];
            __syncthreads();
        }
        // Pass 2: scale each hit row once: out[i] *= 1/(1+deg).
        for (unsigned h = 0; h < nh; h++) {
            unsigned row = g_hits[h].x;
            bool first = true;
            for (unsigned k2 = 0; k2 < h; k2++)
                if (g_hits[k2].x == row) { first = false; break; }
            if (first) {
                int deg = 1;
                for (unsigned k2 = h + 1; k2 < nh; k2++)
                    if (g_hits[k2].x == row) deg++;
                if (tid < DMEM)
                    out[(size_t)row * DMEM + tid] *= 1.0f / (1.0f + (float)deg);
            }
            __syncthreads();
        }
    }
}

// ---------------------------------------------------------------------------
extern "C" void kernel_launch(void* const* d_in, const int* in_sizes, int n_in,
                              void* d_out, int out_size) {
    (void)in_sizes; (void)n_in; (void)out_size;
    const float* X  = (const float*)d_in[0];
    const float* W  = (const float*)d_in[1];
    const float* Bv = (const float*)d_in[2];
    float* out = (float*)d_out;

    const int PROJ_SMEM = 2 * TILEB + 512;     // ~66 KB
    const int SIM_SMEM  = 3 * TILEB;           // 96 KB (2 CTAs/SM)
    cudaFuncSetAttribute(proj_kernel, cudaFuncAttributeMaxDynamicSharedMemorySize, PROJ_SMEM);
    cudaFuncSetAttribute(sim_kernel,  cudaFuncAttributeMaxDynamicSharedMemorySize, SIM_SMEM);

    proj_kernel<<<(NBATCH * NROWS) / 128, 256, PROJ_SMEM>>>(X, W, Bv, out);
    sim_kernel<<<SIMGRID, 256, SIM_SMEM>>>(X, out);
}

// round 14
// speedup vs baseline: 1.0961x; 1.0961x over previous
#include <cuda_runtime.h>
#include <cuda_bf16.h>
#include <stdint.h>

// Problem dims (fixed by the dataset)
#define NBATCH 4
#define NROWS  8192
#define DMEM   128
#define NTILES 64
#define TILEB  32768        // 128 rows * 128 bf16 * 2B
#define THRESH 0.65f
#define HITCAP 65536

// Scratch (device globals are the sanctioned scratch mechanism)
__device__ __align__(16) __nv_bfloat16 g_proj[(size_t)NBATCH * NROWS * DMEM]; // 8 MB normalized proj
__device__ uint2 g_hits[HITCAP];
__device__ unsigned g_hitcnt;

// ---------------------------------------------------------------------------
// helpers
// ---------------------------------------------------------------------------
__device__ __forceinline__ uint32_t su32(const void* p) {
    uint32_t a;
    asm("{ .reg .u64 t; cvta.to.shared.u64 t, %1; cvt.u32.u64 %0, t; }" : "=r"(a) : "l"(p));
    return a;
}

#define LDMATRIX_X4(r0, r1, r2, r3, addr) \
    asm volatile("ldmatrix.sync.aligned.m8n8.x4.shared.b16 {%0,%1,%2,%3}, [%4];" \
                 : "=r"(r0), "=r"(r1), "=r"(r2), "=r"(r3) : "r"(addr))

#define MMA_BF16(d, a, b0, b1) \
    asm volatile("mma.sync.aligned.m16n8k16.row.col.f32.bf16.bf16.f32 " \
                 "{%0,%1,%2,%3}, {%4,%5,%6,%7}, {%8,%9}, {%0,%1,%2,%3};" \
                 : "+f"((d)[0]), "+f"((d)[1]), "+f"((d)[2]), "+f"((d)[3]) \
                 : "r"((a)[0]), "r"((a)[1]), "r"((a)[2]), "r"((a)[3]), "r"(b0), "r"(b1))

// bf16 128x128 tile (32KB, 256B rows, 16 chunks/row, c^(r&7) swizzle). 256 thr.
__device__ __forceinline__ void copy_tile16(uint32_t dst, const __nv_bfloat16* src, int tid) {
    #pragma unroll
    for (int k = 0; k < 8; k++) {
        int idx = tid + k * 256;
        int r = idx >> 4, c = idx & 15;
        uint32_t doff = (uint32_t)(r * 256 + ((c ^ (r & 7)) << 4));
        asm volatile("cp.async.cg.shared.global [%0], [%1], 16;"
                     :: "r"(dst + doff), "l"((const char*)src + (size_t)idx * 16) : "memory");
    }
}

// fp32 128x128 tile -> bf16 swizzled smem (ld+cvt+st). 256 threads.
__device__ __forceinline__ void conv_tile(unsigned char* dsm_base, const float* src, int tid) {
    #pragma unroll
    for (int k = 0; k < 8; k++) {
        int idx = tid + k * 256;
        int r = idx >> 4, c = idx & 15;
        const float4* s = reinterpret_cast<const float4*>(src + (size_t)r * DMEM + c * 8);
        float4 f0 = s[0], f1 = s[1];
        __nv_bfloat162 h0 = __floats2bfloat162_rn(f0.x, f0.y);
        __nv_bfloat162 h1 = __floats2bfloat162_rn(f0.z, f0.w);
        __nv_bfloat162 h2 = __floats2bfloat162_rn(f1.x, f1.y);
        __nv_bfloat162 h3 = __floats2bfloat162_rn(f1.z, f1.w);
        *reinterpret_cast<uint4*>(dsm_base + r * 256 + ((c ^ (r & 7)) << 4)) =
            make_uint4(*(uint32_t*)&h0, *(uint32_t*)&h1, *(uint32_t*)&h2, *(uint32_t*)&h3);
    }
}

// Load this warp's resident A fragments (m32 x k128) from swizzled smA.
__device__ __forceinline__ void load_afrags(uint32_t a[2][8][4], uint32_t smA, int wm, int l) {
    #pragma unroll
    for (int m = 0; m < 2; m++)
        #pragma unroll
        for (int k = 0; k < 8; k++) {
            int r = wm * 32 + m * 16 + (l & 15);
            int chunk = k * 2 + ((l >> 4) & 1);
            uint32_t addr = smA + r * 256 + ((chunk ^ (r & 7)) << 4);
            LDMATRIX_X4(a[m][k][0], a[m][k][1], a[m][k][2], a[m][k][3], addr);
        }
}

// ---------------------------------------------------------------------------
// Stage 1 (measured 15.0us): proj = normalize(X @ W^T + b) -> bf16 row-major,
// via bf16 mma. W converted inline; also writes out = X (analytic diagonal).
// 256 CTAs x 256 thr; warp w owns rows w*16..+15, full n=128.
// ---------------------------------------------------------------------------
__global__ void __launch_bounds__(256) proj_kernel(const float* __restrict__ X,
                                                   const float* __restrict__ W,
                                                   const float* __restrict__ Bv,
                                                   float* __restrict__ out) {
    extern __shared__ unsigned char dsm[];
    uint32_t smX = su32(dsm);            // 32 KB (swizzled)
    uint32_t smW = smX + TILEB;          // 32 KB (swizzled)
    float* bs = (float*)(dsm + 2 * TILEB);

    int tid = threadIdx.x, w = tid >> 5, l = tid & 31;
    int r0 = blockIdx.x * 128;

    if (blockIdx.x == 0 && tid == 0) g_hitcnt = 0u;   // reset hit counter
    if (tid < 128) bs[tid] = Bv[tid];

    conv_tile(dsm + TILEB, W, tid);                   // W fp32 -> bf16 smem

    // X fp32 -> bf16 into swizzled smem; forward fp32 to out (out = X).
    #pragma unroll
    for (int k = 0; k < 8; k++) {
        int idx = tid + k * 256;
        int r = idx >> 4, c = idx & 15;
        size_t gbase = ((size_t)(r0 + r) * DMEM + c * 8);
        float4 f0 = reinterpret_cast<const float4*>(X + gbase)[0];
        float4 f1 = reinterpret_cast<const float4*>(X + gbase)[1];
        reinterpret_cast<float4*>(out + gbase)[0] = f0;
        reinterpret_cast<float4*>(out + gbase)[1] = f1;
        __nv_bfloat162 h0 = __floats2bfloat162_rn(f0.x, f0.y);
        __nv_bfloat162 h1 = __floats2bfloat162_rn(f0.z, f0.w);
        __nv_bfloat162 h2 = __floats2bfloat162_rn(f1.x, f1.y);
        __nv_bfloat162 h3 = __floats2bfloat162_rn(f1.z, f1.w);
        *reinterpret_cast<uint4*>(dsm + r * 256 + ((c ^ (r & 7)) << 4)) =
            make_uint4(*(uint32_t*)&h0, *(uint32_t*)&h1, *(uint32_t*)&h2, *(uint32_t*)&h3);
    }
    __syncthreads();

    float acc[16][4];
    #pragma unroll
    for (int f = 0; f < 16; f++)
        #pragma unroll
        for (int p = 0; p < 4; p++) acc[f][p] = 0.f;

    #pragma unroll
    for (int k = 0; k < 8; k++) {
        uint32_t a[4];
        {
            int r = w * 16 + (l & 15);
            int chunk = k * 2 + ((l >> 4) & 1);
            uint32_t addr = smX + r * 256 + ((chunk ^ (r & 7)) << 4);
            LDMATRIX_X4(a[0], a[1], a[2], a[3], addr);
        }
        #pragma unroll
        for (int nf = 0; nf < 8; nf++) {
            int nn = nf * 16 + (l & 7) + ((l & 16) ? 8 : 0);
            int chunk = k * 2 + ((l >> 3) & 1);
            uint32_t addr = smW + nn * 256 + ((chunk ^ (nn & 7)) << 4);
            uint32_t b0, b1, b2, b3;
            LDMATRIX_X4(b0, b1, b2, b3, addr);
            MMA_BF16(acc[nf * 2],     a, b0, b1);
            MMA_BF16(acc[nf * 2 + 1], a, b2, b3);
        }
    }

    // bias + row sums of squares (rows l/4 and l/4+8 of this warp's m16)
    float slo = 0.f, shi = 0.f;
    #pragma unroll
    for (int f = 0; f < 16; f++) {
        int c0 = f * 8 + 2 * (l & 3);
        float b0 = bs[c0], b1 = bs[c0 + 1];
        acc[f][0] += b0; acc[f][1] += b1;
        acc[f][2] += b0; acc[f][3] += b1;
        slo += acc[f][0] * acc[f][0] + acc[f][1] * acc[f][1];
        shi += acc[f][2] * acc[f][2] + acc[f][3] * acc[f][3];
    }
    slo += __shfl_xor_sync(0xffffffffu, slo, 1);
    slo += __shfl_xor_sync(0xffffffffu, slo, 2);
    shi += __shfl_xor_sync(0xffffffffu, shi, 1);
    shi += __shfl_xor_sync(0xffffffffu, shi, 2);
    float rlo = rsqrtf(fmaxf(slo, 1e-24f));
    float rhi = rsqrtf(fmaxf(shi, 1e-24f));

    int rowlo = r0 + w * 16 + (l >> 2);
    #pragma unroll
    for (int f = 0; f < 16; f++) {
        int c0 = f * 8 + 2 * (l & 3);
        __nv_bfloat162 hlo = __floats2bfloat162_rn(acc[f][0] * rlo, acc[f][1] * rlo);
        __nv_bfloat162 hhi = __floats2bfloat162_rn(acc[f][2] * rhi, acc[f][3] * rhi);
        *reinterpret_cast<uint32_t*>(g_proj + (size_t)rowlo * DMEM + c0)       = *(uint32_t*)&hlo;
        *reinterpret_cast<uint32_t*>(g_proj + (size_t)(rowlo + 8) * DMEM + c0) = *(uint32_t*)&hhi;
    }
}

// ---------------------------------------------------------------------------
// Stage 2 (measured-best config): upper-triangular sim tiles (jt >= it) via
// bf16 mma. CTA = (batch, pair p, eighth q): 1024 CTAs x 8-9 tiles
// (granularity curve: x4=98us, x8=88us, x16=91us). Rare hits append (i,j)
// [+ symmetric partner] to a global list. NO extra state in this kernel —
// register allocation at the 128-reg cap is the proven-fragile resource.
// ---------------------------------------------------------------------------
__global__ void __launch_bounds__(256, 2) sim_kernel() {
    extern __shared__ unsigned char dsm[];
    uint32_t smA  = su32(dsm);
    uint32_t smB0 = smA + TILEB;
    uint32_t smB1 = smA + 2 * TILEB;

    int tid = threadIdx.x, wid = tid >> 5, l = tid & 31;
    int wm = wid >> 1, wn = wid & 1;

    int bid = blockIdx.x;
    int batch = bid >> 8;
    int p     = (bid >> 3) & 31;
    int q     = bid & 7;
    int n0    = NTILES - p;                 // tiles in row p
    int t0 = (q * 65) >> 3, t1 = ((q + 1) * 65) >> 3;

    const __nv_bfloat16* pb = g_proj + (size_t)batch * NROWS * DMEM;
    int bi = batch * NROWS;                 // global row offset for this batch

    #define JOF(t) (((t) < n0) ? (p + (t)) : ((63 - p) + ((t) - n0)))
    #define IOF(t) (((t) < n0) ? p : (63 - p))

    int cur_i = IOF(t0);
    copy_tile16(smA, pb + (size_t)cur_i * 128 * DMEM, tid);
    copy_tile16(smB0, pb + (size_t)JOF(t0) * 128 * DMEM, tid);
    asm volatile("cp.async.commit_group;" ::: "memory");
    if (t0 + 1 < t1)
        copy_tile16(smB1, pb + (size_t)JOF(t0 + 1) * 128 * DMEM, tid);
    asm volatile("cp.async.commit_group;" ::: "memory");
    asm volatile("cp.async.wait_group 1;" ::: "memory");
    __syncthreads();

    uint32_t a[2][8][4];
    load_afrags(a, smA, wm, l);

    for (int t = t0; t < t1; t++) {
        if (IOF(t) != cur_i) {             // row crossing (only 1-in-8 CTAs)
            cur_i = IOF(t);
            __syncthreads();
            copy_tile16(smA, pb + (size_t)cur_i * 128 * DMEM, tid);
            asm volatile("cp.async.commit_group;" ::: "memory");
            asm volatile("cp.async.wait_group 0;" ::: "memory");
            __syncthreads();
            load_afrags(a, smA, wm, l);
        }
        int it = cur_i, jt = JOF(t);
        uint32_t smB = ((t - t0) & 1) ? smB1 : smB0;

        #pragma unroll 1
        for (int g = 0; g < 4; g++) {
            int n0c = wn * 64 + g * 16;
            float d[2][2][4];
            #pragma unroll
            for (int m = 0; m < 2; m++)
                #pragma unroll
                for (int h = 0; h < 2; h++)
                    #pragma unroll
                    for (int pp = 0; pp < 4; pp++) d[m][h][pp] = 0.f;

            #pragma unroll
            for (int k = 0; k < 8; k++) {
                int nn = n0c + (l & 7) + ((l & 16) ? 8 : 0);
                int chunk = k * 2 + ((l >> 3) & 1);
                uint32_t addr = smB + nn * 256 + ((chunk ^ (nn & 7)) << 4);
                uint32_t b0, b1, b2, b3;
                LDMATRIX_X4(b0, b1, b2, b3, addr);
                #pragma unroll
                for (int m = 0; m < 2; m++) {
                    MMA_BF16(d[m][0], a[m][k], b0, b1);
                    MMA_BF16(d[m][1], a[m][k], b2, b3);
                }
            }

            float vmax = d[0][0][0];
            #pragma unroll
            for (int m = 0; m < 2; m++)
                #pragma unroll
                for (int h = 0; h < 2; h++)
                    #pragma unroll
                    for (int pp = 0; pp < 4; pp++) vmax = fmaxf(vmax, d[m][h][pp]);
            unsigned warp_any = __ballot_sync(0xffffffffu, vmax > THRESH);

            if (warp_any) {   // rare: diagonal tile self-sim, or a true hit
                bool diag = (it == jt);
                #pragma unroll
                for (int m = 0; m < 2; m++)
                    #pragma unroll
                    for (int h = 0; h < 2; h++)
                        #pragma unroll
                        for (int pp = 0; pp < 4; pp++) {
                            if (d[m][h][pp] > THRESH) {
                                int ib = bi + it * 128 + wm * 32 + m * 16 + (l >> 2) + ((pp & 2) ? 8 : 0);
                                int jb = bi + jt * 128 + n0c + h * 8 + 2 * (l & 3) + (pp & 1);
                                if (ib != jb) {
                                    unsigned idx = atomicAdd(&g_hitcnt, diag ? 1u : 2u);
                                    if (idx < HITCAP)
                                        g_hits[idx] = make_uint2((unsigned)ib, (unsigned)jb);
                                    if (!diag && idx + 1 < HITCAP)
                                        g_hits[idx + 1] = make_uint2((unsigned)jb, (unsigned)ib);
                                }
                            }
                        }
            }
        }

        __syncthreads();
        if (t + 2 < t1)
            copy_tile16(smB, pb + (size_t)JOF(t + 2) * 128 * DMEM, tid);
        asm volatile("cp.async.commit_group;" ::: "memory");
        asm volatile("cp.async.wait_group 1;" ::: "memory");
        __syncthreads();
    }
    #undef JOF
    #undef IOF
}

// ---------------------------------------------------------------------------
// Stage 3 (merged hits+fin, measured 4.2us): per row, scan the (tiny) hit
// list; if this row has hits: out[row] = (X[row] + sum_j X[j]) / (1 + deg).
// Else untouched (out already holds X from proj).
// ---------------------------------------------------------------------------
__global__ void __launch_bounds__(256) fin_kernel(const float* __restrict__ X,
                                                  float* __restrict__ out) {
    unsigned row = blockIdx.x * 256 + threadIdx.x;
    unsigned nh = g_hitcnt;
    if (nh > HITCAP) nh = HITCAP;
    int deg = 0;
    for (unsigned h = 0; h < nh; h++)
        if (g_hits[h].x == row) deg++;
    if (deg > 0) {
        float inv = 1.0f / (1.0f + (float)deg);
        float* o = out + (size_t)row * DMEM;
        #pragma unroll 4
        for (int dcol = 0; dcol < DMEM; dcol++) {
            float acc = o[dcol];                      // == X[row][dcol]
            for (unsigned h = 0; h < nh; h++)
                if (g_hits[h].x == row)
                    acc += X[(size_t)g_hits[h].y * DMEM + dcol];
            o[dcol] = acc * inv;
        }
    }
}

// ---------------------------------------------------------------------------
extern "C" void kernel_launch(void* const* d_in, const int* in_sizes, int n_in,
                              void* d_out, int out_size) {
    (void)in_sizes; (void)n_in; (void)out_size;
    const float* X  = (const float*)d_in[0];
    const float* W  = (const float*)d_in[1];
    const float* Bv = (const float*)d_in[2];
    float* out = (float*)d_out;

    const int PROJ_SMEM = 2 * TILEB + 512;     // ~66 KB
    const int SIM_SMEM  = 3 * TILEB;           // 96 KB (2 CTAs/SM)
    cudaFuncSetAttribute(proj_kernel, cudaFuncAttributeMaxDynamicSharedMemorySize, PROJ_SMEM);
    cudaFuncSetAttribute(sim_kernel,  cudaFuncAttributeMaxDynamicSharedMemorySize, SIM_SMEM);

    proj_kernel<<<(NBATCH * NROWS) / 128, 256, PROJ_SMEM>>>(X, W, Bv, out);
    sim_kernel<<<NBATCH * 32 * 8, 256, SIM_SMEM>>>();
    fin_kernel<<<NBATCH * NROWS / 256, 256>>>(X, out);
}

// round 15
// speedup vs baseline: 1.6584x; 1.5129x over previous
#include <cuda_runtime.h>
#include <cuda_bf16.h>
#include <stdint.h>

// Problem dims (fixed by the dataset)
#define NBATCH 4
#define NROWS  8192
#define DMEM   128
#define NTILES 64
#define TILEB  32768        // bf16 tile bytes (proj kernel smem)
#define TILE8  16384        // s8 tile bytes: 128 rows * 128 B
#define THRESH 0.65f
#define THRESHI 10483       // floor(0.65 * 127 * 127): dot_int > 10483 <=> sim > 0.65
#define HITCAP 65536

// Scratch (device globals are the sanctioned scratch mechanism)
__device__ __align__(16) int8_t g_proj[(size_t)NBATCH * NROWS * DMEM];  // 4 MB s8 proj (scale 1/127)
__device__ uint2 g_hits[HITCAP];
__device__ unsigned g_hitcnt;

// ---------------------------------------------------------------------------
// helpers
// ---------------------------------------------------------------------------
__device__ __forceinline__ uint32_t su32(const void* p) {
    uint32_t a;
    asm("{ .reg .u64 t; cvta.to.shared.u64 t, %1; cvt.u32.u64 %0, t; }" : "=r"(a) : "l"(p));
    return a;
}

#define LDMATRIX_X4(r0, r1, r2, r3, addr) \
    asm volatile("ldmatrix.sync.aligned.m8n8.x4.shared.b16 {%0,%1,%2,%3}, [%4];" \
                 : "=r"(r0), "=r"(r1), "=r"(r2), "=r"(r3) : "r"(addr))

#define MMA_BF16(d, a, b0, b1) \
    asm volatile("mma.sync.aligned.m16n8k16.row.col.f32.bf16.bf16.f32 " \
                 "{%0,%1,%2,%3}, {%4,%5,%6,%7}, {%8,%9}, {%0,%1,%2,%3};" \
                 : "+f"((d)[0]), "+f"((d)[1]), "+f"((d)[2]), "+f"((d)[3]) \
                 : "r"((a)[0]), "r"((a)[1]), "r"((a)[2]), "r"((a)[3]), "r"(b0), "r"(b1))

#define MMA_S8(d, a, b0, b1) \
    asm volatile("mma.sync.aligned.m16n8k32.row.col.s32.s8.s8.s32 " \
                 "{%0,%1,%2,%3}, {%4,%5,%6,%7}, {%8,%9}, {%0,%1,%2,%3};" \
                 : "+r"((d)[0]), "+r"((d)[1]), "+r"((d)[2]), "+r"((d)[3]) \
                 : "r"((a)[0]), "r"((a)[1]), "r"((a)[2]), "r"((a)[3]), "r"(b0), "r"(b1))

// bf16 128x128 tile (32KB, 256B rows, 16 chunks/row, c^(r&7) swizzle). 256 thr.
__device__ __forceinline__ void copy_tile16(uint32_t dst, const __nv_bfloat16* src, int tid) {
    #pragma unroll
    for (int k = 0; k < 8; k++) {
        int idx = tid + k * 256;
        int r = idx >> 4, c = idx & 15;
        uint32_t doff = (uint32_t)(r * 256 + ((c ^ (r & 7)) << 4));
        asm volatile("cp.async.cg.shared.global [%0], [%1], 16;"
                     :: "r"(dst + doff), "l"((const char*)src + (size_t)idx * 16) : "memory");
    }
}

// s8 128x128 tile (16KB, 128B rows, 8 chunks/row, c^(r&7) swizzle). 256 thr.
// Layout validated in the R3 fp8 kernel (rel_err 0.0).
__device__ __forceinline__ void copy_tile8(uint32_t dst, const int8_t* src, int tid) {
    #pragma unroll
    for (int k = 0; k < 4; k++) {
        int idx = tid + k * 256;
        int r = idx >> 3, c = idx & 7;
        uint32_t doff = (uint32_t)(r * 128 + ((c ^ (r & 7)) << 4));
        asm volatile("cp.async.cg.shared.global [%0], [%1], 16;"
                     :: "r"(dst + doff), "l"((const char*)src + (size_t)idx * 16) : "memory");
    }
}

// fp32 128x128 tile -> bf16 swizzled smem (ld+cvt+st). 256 threads.
__device__ __forceinline__ void conv_tile(unsigned char* dsm_base, const float* src, int tid) {
    #pragma unroll
    for (int k = 0; k < 8; k++) {
        int idx = tid + k * 256;
        int r = idx >> 4, c = idx & 15;
        const float4* s = reinterpret_cast<const float4*>(src + (size_t)r * DMEM + c * 8);
        float4 f0 = s[0], f1 = s[1];
        __nv_bfloat162 h0 = __floats2bfloat162_rn(f0.x, f0.y);
        __nv_bfloat162 h1 = __floats2bfloat162_rn(f0.z, f0.w);
        __nv_bfloat162 h2 = __floats2bfloat162_rn(f1.x, f1.y);
        __nv_bfloat162 h3 = __floats2bfloat162_rn(f1.z, f1.w);
        *reinterpret_cast<uint4*>(dsm_base + r * 256 + ((c ^ (r & 7)) << 4)) =
            make_uint4(*(uint32_t*)&h0, *(uint32_t*)&h1, *(uint32_t*)&h2, *(uint32_t*)&h3);
    }
}

// Load this warp's resident A fragments (m32 x k128, s8) from swizzled smA.
__device__ __forceinline__ void load_afrags8(uint32_t a[2][4][4], uint32_t smA, int wm, int l) {
    #pragma unroll
    for (int m = 0; m < 2; m++)
        #pragma unroll
        for (int k = 0; k < 4; k++) {
            int r = wm * 32 + m * 16 + (l & 15);
            int chunk = k * 2 + ((l >> 4) & 1);
            uint32_t addr = smA + r * 128 + ((chunk ^ (r & 7)) << 4);
            LDMATRIX_X4(a[m][k][0], a[m][k][1], a[m][k][2], a[m][k][3], addr);
        }
}

// ---------------------------------------------------------------------------
// Stage 1: proj = normalize(X @ W^T + b) -> s8 (scale 127), via bf16 mma.
// W converted inline; also writes out = X (analytic diagonal). 256 CTAs.
// ---------------------------------------------------------------------------
__global__ void __launch_bounds__(256) proj_kernel(const float* __restrict__ X,
                                                   const float* __restrict__ W,
                                                   const float* __restrict__ Bv,
                                                   float* __restrict__ out) {
    extern __shared__ unsigned char dsm[];
    uint32_t smX = su32(dsm);            // 32 KB (swizzled)
    uint32_t smW = smX + TILEB;          // 32 KB (swizzled)
    float* bs = (float*)(dsm + 2 * TILEB);

    int tid = threadIdx.x, w = tid >> 5, l = tid & 31;
    int r0 = blockIdx.x * 128;

    if (blockIdx.x == 0 && tid == 0) g_hitcnt = 0u;   // reset hit counter
    if (tid < 128) bs[tid] = Bv[tid];

    conv_tile(dsm + TILEB, W, tid);                   // W fp32 -> bf16 smem

    // X fp32 -> bf16 into swizzled smem; forward fp32 to out (out = X).
    #pragma unroll
    for (int k = 0; k < 8; k++) {
        int idx = tid + k * 256;
        int r = idx >> 4, c = idx & 15;
        size_t gbase = ((size_t)(r0 + r) * DMEM + c * 8);
        float4 f0 = reinterpret_cast<const float4*>(X + gbase)[0];
        float4 f1 = reinterpret_cast<const float4*>(X + gbase)[1];
        reinterpret_cast<float4*>(out + gbase)[0] = f0;
        reinterpret_cast<float4*>(out + gbase)[1] = f1;
        __nv_bfloat162 h0 = __floats2bfloat162_rn(f0.x, f0.y);
        __nv_bfloat162 h1 = __floats2bfloat162_rn(f0.z, f0.w);
        __nv_bfloat162 h2 = __floats2bfloat162_rn(f1.x, f1.y);
        __nv_bfloat162 h3 = __floats2bfloat162_rn(f1.z, f1.w);
        *reinterpret_cast<uint4*>(dsm + r * 256 + ((c ^ (r & 7)) << 4)) =
            make_uint4(*(uint32_t*)&h0, *(uint32_t*)&h1, *(uint32_t*)&h2, *(uint32_t*)&h3);
    }
    __syncthreads();

    float acc[16][4];
    #pragma unroll
    for (int f = 0; f < 16; f++)
        #pragma unroll
        for (int p = 0; p < 4; p++) acc[f][p] = 0.f;

    #pragma unroll
    for (int k = 0; k < 8; k++) {
        uint32_t a[4];
        {
            int r = w * 16 + (l & 15);
            int chunk = k * 2 + ((l >> 4) & 1);
            uint32_t addr = smX + r * 256 + ((chunk ^ (r & 7)) << 4);
            LDMATRIX_X4(a[0], a[1], a[2], a[3], addr);
        }
        #pragma unroll
        for (int nf = 0; nf < 8; nf++) {
            int nn = nf * 16 + (l & 7) + ((l & 16) ? 8 : 0);
            int chunk = k * 2 + ((l >> 3) & 1);
            uint32_t addr = smW + nn * 256 + ((chunk ^ (nn & 7)) << 4);
            uint32_t b0, b1, b2, b3;
            LDMATRIX_X4(b0, b1, b2, b3, addr);
            MMA_BF16(acc[nf * 2],     a, b0, b1);
            MMA_BF16(acc[nf * 2 + 1], a, b2, b3);
        }
    }

    // bias + row sums of squares (rows l/4 and l/4+8 of this warp's m16)
    float slo = 0.f, shi = 0.f;
    #pragma unroll
    for (int f = 0; f < 16; f++) {
        int c0 = f * 8 + 2 * (l & 3);
        float b0 = bs[c0], b1 = bs[c0 + 1];
        acc[f][0] += b0; acc[f][1] += b1;
        acc[f][2] += b0; acc[f][3] += b1;
        slo += acc[f][0] * acc[f][0] + acc[f][1] * acc[f][1];
        shi += acc[f][2] * acc[f][2] + acc[f][3] * acc[f][3];
    }
    slo += __shfl_xor_sync(0xffffffffu, slo, 1);
    slo += __shfl_xor_sync(0xffffffffu, slo, 2);
    shi += __shfl_xor_sync(0xffffffffu, shi, 1);
    shi += __shfl_xor_sync(0xffffffffu, shi, 2);
    float rlo = rsqrtf(fmaxf(slo, 1e-24f)) * 127.0f;   // fold s8 scale in
    float rhi = rsqrtf(fmaxf(shi, 1e-24f)) * 127.0f;

    int rowlo = r0 + w * 16 + (l >> 2);
    #pragma unroll
    for (int f = 0; f < 16; f++) {
        int c0 = f * 8 + 2 * (l & 3);
        int q0 = __float2int_rn(acc[f][0] * rlo);
        int q1 = __float2int_rn(acc[f][1] * rlo);
        int q2 = __float2int_rn(acc[f][2] * rhi);
        int q3 = __float2int_rn(acc[f][3] * rhi);
        uint16_t plo = (uint16_t)((q0 & 0xff) | ((q1 & 0xff) << 8));
        uint16_t phi = (uint16_t)((q2 & 0xff) | ((q3 & 0xff) << 8));
        *reinterpret_cast<uint16_t*>(g_proj + (size_t)rowlo * DMEM + c0)       = plo;
        *reinterpret_cast<uint16_t*>(g_proj + (size_t)(rowlo + 8) * DMEM + c0) = phi;
    }
}

// ---------------------------------------------------------------------------
// Stage 2: upper-triangular sim tiles (jt >= it) via s8 IMMA (m16n8k32).
// 1024 CTAs x 8-9 tiles (measured-optimal granularity). Integer threshold
// dot > 10483 == sim > 0.65. Rare hits append (i,j) [+ partner] to list.
// ---------------------------------------------------------------------------
__global__ void __launch_bounds__(256, 2) sim_kernel() {
    extern __shared__ unsigned char dsm[];
    uint32_t smA  = su32(dsm);
    uint32_t smB0 = smA + TILE8;
    uint32_t smB1 = smA + 2 * TILE8;

    int tid = threadIdx.x, wid = tid >> 5, l = tid & 31;
    int wm = wid >> 1, wn = wid & 1;

    int bid = blockIdx.x;
    int batch = bid >> 8;
    int p     = (bid >> 3) & 31;
    int q     = bid & 7;
    int n0    = NTILES - p;                 // tiles in row p
    int t0 = (q * 65) >> 3, t1 = ((q + 1) * 65) >> 3;

    const int8_t* pb = g_proj + (size_t)batch * NROWS * DMEM;
    int bi = batch * NROWS;                 // global row offset for this batch

    #define JOF(t) (((t) < n0) ? (p + (t)) : ((63 - p) + ((t) - n0)))
    #define IOF(t) (((t) < n0) ? p : (63 - p))

    int cur_i = IOF(t0);
    copy_tile8(smA, pb + (size_t)cur_i * 128 * DMEM, tid);
    copy_tile8(smB0, pb + (size_t)JOF(t0) * 128 * DMEM, tid);
    asm volatile("cp.async.commit_group;" ::: "memory");
    if (t0 + 1 < t1)
        copy_tile8(smB1, pb + (size_t)JOF(t0 + 1) * 128 * DMEM, tid);
    asm volatile("cp.async.commit_group;" ::: "memory");
    asm volatile("cp.async.wait_group 1;" ::: "memory");
    __syncthreads();

    uint32_t a[2][4][4];
    load_afrags8(a, smA, wm, l);

    for (int t = t0; t < t1; t++) {
        if (IOF(t) != cur_i) {             // row crossing (only 1-in-8 CTAs)
            cur_i = IOF(t);
            __syncthreads();
            copy_tile8(smA, pb + (size_t)cur_i * 128 * DMEM, tid);
            asm volatile("cp.async.commit_group;" ::: "memory");
            asm volatile("cp.async.wait_group 0;" ::: "memory");
            __syncthreads();
            load_afrags8(a, smA, wm, l);
        }
        int it = cur_i, jt = JOF(t);
        uint32_t smB = ((t - t0) & 1) ? smB1 : smB0;

        #pragma unroll 1
        for (int g = 0; g < 4; g++) {
            int n0c = wn * 64 + g * 16;
            int d[2][2][4];
            #pragma unroll
            for (int m = 0; m < 2; m++)
                #pragma unroll
                for (int h = 0; h < 2; h++)
                    #pragma unroll
                    for (int pp = 0; pp < 4; pp++) d[m][h][pp] = 0;

            #pragma unroll
            for (int k = 0; k < 4; k++) {
                int nn = n0c + (l & 7) + ((l & 16) ? 8 : 0);
                int chunk = k * 2 + ((l >> 3) & 1);
                uint32_t addr = smB + nn * 128 + ((chunk ^ (nn & 7)) << 4);
                uint32_t b0, b1, b2, b3;
                LDMATRIX_X4(b0, b1, b2, b3, addr);
                #pragma unroll
                for (int m = 0; m < 2; m++) {
                    MMA_S8(d[m][0], (uint32_t*)a[m][k], b0, b1);
                    MMA_S8(d[m][1], (uint32_t*)a[m][k], b2, b3);
                }
            }

            int vmax = d[0][0][0];
            #pragma unroll
            for (int m = 0; m < 2; m++)
                #pragma unroll
                for (int h = 0; h < 2; h++)
                    #pragma unroll
                    for (int pp = 0; pp < 4; pp++) vmax = max(vmax, d[m][h][pp]);
            unsigned warp_any = __ballot_sync(0xffffffffu, vmax > THRESHI);

            if (warp_any) {   // rare: diagonal tile self-sim, or a true hit
                bool diag = (it == jt);
                #pragma unroll
                for (int m = 0; m < 2; m++)
                    #pragma unroll
                    for (int h = 0; h < 2; h++)
                        #pragma unroll
                        for (int pp = 0; pp < 4; pp++) {
                            if (d[m][h][pp] > THRESHI) {
                                int ib = bi + it * 128 + wm * 32 + m * 16 + (l >> 2) + ((pp & 2) ? 8 : 0);
                                int jb = bi + jt * 128 + n0c + h * 8 + 2 * (l & 3) + (pp & 1);
                                if (ib != jb) {
                                    unsigned idx = atomicAdd(&g_hitcnt, diag ? 1u : 2u);
                                    if (idx < HITCAP)
                                        g_hits[idx] = make_uint2((unsigned)ib, (unsigned)jb);
                                    if (!diag && idx + 1 < HITCAP)
                                        g_hits[idx + 1] = make_uint2((unsigned)jb, (unsigned)ib);
                                }
                            }
                        }
            }
        }

        __syncthreads();
        if (t + 2 < t1)
            copy_tile8(smB, pb + (size_t)JOF(t + 2) * 128 * DMEM, tid);
        asm volatile("cp.async.commit_group;" ::: "memory");
        asm volatile("cp.async.wait_group 1;" ::: "memory");
        __syncthreads();
    }
    #undef JOF
    #undef IOF
}

// ---------------------------------------------------------------------------
// Stage 3 (merged hits+fin, measured 4.2us): per row, scan the (tiny) hit
// list; if this row has hits: out[row] = (X[row] + sum_j X[j]) / (1 + deg).
// Else untouched (out already holds X from proj).
// ---------------------------------------------------------------------------
__global__ void __launch_bounds__(256) fin_kernel(const float* __restrict__ X,
                                                  float* __restrict__ out) {
    unsigned row = blockIdx.x * 256 + threadIdx.x;
    unsigned nh = g_hitcnt;
    if (nh > HITCAP) nh = HITCAP;
    int deg = 0;
    for (unsigned h = 0; h < nh; h++)
        if (g_hits[h].x == row) deg++;
    if (deg > 0) {
        float inv = 1.0f / (1.0f + (float)deg);
        float* o = out + (size_t)row * DMEM;
        #pragma unroll 4
        for (int dcol = 0; dcol < DMEM; dcol++) {
            float acc = o[dcol];                      // == X[row][dcol]
            for (unsigned h = 0; h < nh; h++)
                if (g_hits[h].x == row)
                    acc += X[(size_t)g_hits[h].y * DMEM + dcol];
            o[dcol] = acc * inv;
        }
    }
}

// ---------------------------------------------------------------------------
extern "C" void kernel_launch(void* const* d_in, const int* in_sizes, int n_in,
                              void* d_out, int out_size) {
    (void)in_sizes; (void)n_in; (void)out_size;
    const float* X  = (const float*)d_in[0];
    const float* W  = (const float*)d_in[1];
    const float* Bv = (const float*)d_in[2];
    float* out = (float*)d_out;

    const int PROJ_SMEM = 2 * TILEB + 512;     // ~66 KB
    const int SIM_SMEM  = 3 * TILE8;           // 48 KB (2 CTAs/SM, reg-capped)
    cudaFuncSetAttribute(proj_kernel, cudaFuncAttributeMaxDynamicSharedMemorySize, PROJ_SMEM);
    cudaFuncSetAttribute(sim_kernel,  cudaFuncAttributeMaxDynamicSharedMemorySize, SIM_SMEM);

    proj_kernel<<<(NBATCH * NROWS) / 128, 256, PROJ_SMEM>>>(X, W, Bv, out);
    sim_kernel<<<NBATCH * 32 * 8, 256, SIM_SMEM>>>();
    fin_kernel<<<NBATCH * NROWS / 256, 256>>>(X, out);
}

// round 17
// speedup vs baseline: 1.7070x; 1.0293x over previous
#include <cuda_runtime.h>
#include <cuda_bf16.h>
#include <stdint.h>

// Problem dims (fixed by the dataset)
#define NBATCH 4
#define NROWS  8192
#define DMEM   128
#define NTILES 64
#define TILEB  32768        // bf16 tile bytes (proj kernel smem)
#define TILE8  16384        // s8 tile bytes: 128 rows * 128 B
#define THRESH 0.65f
#define THRESHI 10483       // floor(0.65 * 127 * 127): dot_int > 10483 <=> sim > 0.65
#define HITCAP 65536

// Scratch (device globals are the sanctioned scratch mechanism)
__device__ __align__(16) int8_t g_proj[(size_t)NBATCH * NROWS * DMEM];  // 4 MB s8 proj (scale 1/127)
__device__ uint2 g_hits[HITCAP];
__device__ unsigned g_hitcnt;

// ---------------------------------------------------------------------------
// helpers
// ---------------------------------------------------------------------------
__device__ __forceinline__ uint32_t su32(const void* p) {
    uint32_t a;
    asm("{ .reg .u64 t; cvta.to.shared.u64 t, %1; cvt.u32.u64 %0, t; }" : "=r"(a) : "l"(p));
    return a;
}

#define LDMATRIX_X4(r0, r1, r2, r3, addr) \
    asm volatile("ldmatrix.sync.aligned.m8n8.x4.shared.b16 {%0,%1,%2,%3}, [%4];" \
                 : "=r"(r0), "=r"(r1), "=r"(r2), "=r"(r3) : "r"(addr))

#define MMA_BF16(d, a, b0, b1) \
    asm volatile("mma.sync.aligned.m16n8k16.row.col.f32.bf16.bf16.f32 " \
                 "{%0,%1,%2,%3}, {%4,%5,%6,%7}, {%8,%9}, {%0,%1,%2,%3};" \
                 : "+f"((d)[0]), "+f"((d)[1]), "+f"((d)[2]), "+f"((d)[3]) \
                 : "r"((a)[0]), "r"((a)[1]), "r"((a)[2]), "r"((a)[3]), "r"(b0), "r"(b1))

#define MMA_S8(d, a, b0, b1) \
    asm volatile("mma.sync.aligned.m16n8k32.row.col.s32.s8.s8.s32 " \
                 "{%0,%1,%2,%3}, {%4,%5,%6,%7}, {%8,%9}, {%0,%1,%2,%3};" \
                 : "+r"((d)[0]), "+r"((d)[1]), "+r"((d)[2]), "+r"((d)[3]) \
                 : "r"((a)[0]), "r"((a)[1]), "r"((a)[2]), "r"((a)[3]), "r"(b0), "r"(b1))

// bf16 128x128 tile (32KB, 256B rows, 16 chunks/row, c^(r&7) swizzle). 256 thr.
__device__ __forceinline__ void copy_tile16(uint32_t dst, const __nv_bfloat16* src, int tid) {
    #pragma unroll
    for (int k = 0; k < 8; k++) {
        int idx = tid + k * 256;
        int r = idx >> 4, c = idx & 15;
        uint32_t doff = (uint32_t)(r * 256 + ((c ^ (r & 7)) << 4));
        asm volatile("cp.async.cg.shared.global [%0], [%1], 16;"
                     :: "r"(dst + doff), "l"((const char*)src + (size_t)idx * 16) : "memory");
    }
}

// s8 128x128 tile (16KB, 128B rows, 8 chunks/row, c^(r&7) swizzle). 256 thr.
__device__ __forceinline__ void copy_tile8(uint32_t dst, const int8_t* src, int tid) {
    #pragma unroll
    for (int k = 0; k < 4; k++) {
        int idx = tid + k * 256;
        int r = idx >> 3, c = idx & 7;
        uint32_t doff = (uint32_t)(r * 128 + ((c ^ (r & 7)) << 4));
        asm volatile("cp.async.cg.shared.global [%0], [%1], 16;"
                     :: "r"(dst + doff), "l"((const char*)src + (size_t)idx * 16) : "memory");
    }
}

// fp32 128x128 tile -> bf16 swizzled smem (ld+cvt+st). 256 threads.
__device__ __forceinline__ void conv_tile(unsigned char* dsm_base, const float* src, int tid) {
    #pragma unroll
    for (int k = 0; k < 8; k++) {
        int idx = tid + k * 256;
        int r = idx >> 4, c = idx & 15;
        const float4* s = reinterpret_cast<const float4*>(src + (size_t)r * DMEM + c * 8);
        float4 f0 = s[0], f1 = s[1];
        __nv_bfloat162 h0 = __floats2bfloat162_rn(f0.x, f0.y);
        __nv_bfloat162 h1 = __floats2bfloat162_rn(f0.z, f0.w);
        __nv_bfloat162 h2 = __floats2bfloat162_rn(f1.x, f1.y);
        __nv_bfloat162 h3 = __floats2bfloat162_rn(f1.z, f1.w);
        *reinterpret_cast<uint4*>(dsm_base + r * 256 + ((c ^ (r & 7)) << 4)) =
            make_uint4(*(uint32_t*)&h0, *(uint32_t*)&h1, *(uint32_t*)&h2, *(uint32_t*)&h3);
    }
}

// Load this warp's resident A fragments (m32 x k128, s8) from swizzled smA.
__device__ __forceinline__ void load_afrags8(uint32_t a[2][4][4], uint32_t smA, int wm, int l) {
    #pragma unroll
    for (int m = 0; m < 2; m++)
        #pragma unroll
        for (int k = 0; k < 4; k++) {
            int r = wm * 32 + m * 16 + (l & 15);
            int chunk = k * 2 + ((l >> 4) & 1);
            uint32_t addr = smA + r * 128 + ((chunk ^ (r & 7)) << 4);
            LDMATRIX_X4(a[m][k][0], a[m][k][1], a[m][k][2], a[m][k][3], addr);
        }
}

// ---------------------------------------------------------------------------
// Stage 1: proj = normalize(X @ W^T + b) -> s8 (scale 127), via bf16 mma.
// W converted inline; also writes out = X (analytic diagonal). 256 CTAs.
// ---------------------------------------------------------------------------
__global__ void __launch_bounds__(256) proj_kernel(const float* __restrict__ X,
                                                   const float* __restrict__ W,
                                                   const float* __restrict__ Bv,
                                                   float* __restrict__ out) {
    extern __shared__ unsigned char dsm[];
    uint32_t smX = su32(dsm);            // 32 KB (swizzled)
    uint32_t smW = smX + TILEB;          // 32 KB (swizzled)
    float* bs = (float*)(dsm + 2 * TILEB);

    int tid = threadIdx.x, w = tid >> 5, l = tid & 31;
    int r0 = blockIdx.x * 128;

    if (blockIdx.x == 0 && tid == 0) g_hitcnt = 0u;   // reset hit counter
    if (tid < 128) bs[tid] = Bv[tid];

    conv_tile(dsm + TILEB, W, tid);                   // W fp32 -> bf16 smem

    // X fp32 -> bf16 into swizzled smem; forward fp32 to out (out = X).
    #pragma unroll
    for (int k = 0; k < 8; k++) {
        int idx = tid + k * 256;
        int r = idx >> 4, c = idx & 15;
        size_t gbase = ((size_t)(r0 + r) * DMEM + c * 8);
        float4 f0 = reinterpret_cast<const float4*>(X + gbase)[0];
        float4 f1 = reinterpret_cast<const float4*>(X + gbase)[1];
        reinterpret_cast<float4*>(out + gbase)[0] = f0;
        reinterpret_cast<float4*>(out + gbase)[1] = f1;
        __nv_bfloat162 h0 = __floats2bfloat162_rn(f0.x, f0.y);
        __nv_bfloat162 h1 = __floats2bfloat162_rn(f0.z, f0.w);
        __nv_bfloat162 h2 = __floats2bfloat162_rn(f1.x, f1.y);
        __nv_bfloat162 h3 = __floats2bfloat162_rn(f1.z, f1.w);
        *reinterpret_cast<uint4*>(dsm + r * 256 + ((c ^ (r & 7)) << 4)) =
            make_uint4(*(uint32_t*)&h0, *(uint32_t*)&h1, *(uint32_t*)&h2, *(uint32_t*)&h3);
    }
    __syncthreads();

    float acc[16][4];
    #pragma unroll
    for (int f = 0; f < 16; f++)
        #pragma unroll
        for (int p = 0; p < 4; p++) acc[f][p] = 0.f;

    #pragma unroll
    for (int k = 0; k < 8; k++) {
        uint32_t a[4];
        {
            int r = w * 16 + (l & 15);
            int chunk = k * 2 + ((l >> 4) & 1);
            uint32_t addr = smX + r * 256 + ((chunk ^ (r & 7)) << 4);
            LDMATRIX_X4(a[0], a[1], a[2], a[3], addr);
        }
        #pragma unroll
        for (int nf = 0; nf < 8; nf++) {
            int nn = nf * 16 + (l & 7) + ((l & 16) ? 8 : 0);
            int chunk = k * 2 + ((l >> 3) & 1);
            uint32_t addr = smW + nn * 256 + ((chunk ^ (nn & 7)) << 4);
            uint32_t b0, b1, b2, b3;
            LDMATRIX_X4(b0, b1, b2, b3, addr);
            MMA_BF16(acc[nf * 2],     a, b0, b1);
            MMA_BF16(acc[nf * 2 + 1], a, b2, b3);
        }
    }

    // bias + row sums of squares (rows l/4 and l/4+8 of this warp's m16)
    float slo = 0.f, shi = 0.f;
    #pragma unroll
    for (int f = 0; f < 16; f++) {
        int c0 = f * 8 + 2 * (l & 3);
        float b0 = bs[c0], b1 = bs[c0 + 1];
        acc[f][0] += b0; acc[f][1] += b1;
        acc[f][2] += b0; acc[f][3] += b1;
        slo += acc[f][0] * acc[f][0] + acc[f][1] * acc[f][1];
        shi += acc[f][2] * acc[f][2] + acc[f][3] * acc[f][3];
    }
    slo += __shfl_xor_sync(0xffffffffu, slo, 1);
    slo += __shfl_xor_sync(0xffffffffu, slo, 2);
    shi += __shfl_xor_sync(0xffffffffu, shi, 1);
    shi += __shfl_xor_sync(0xffffffffu, shi, 2);
    float rlo = rsqrtf(fmaxf(slo, 1e-24f)) * 127.0f;   // fold s8 scale in
    float rhi = rsqrtf(fmaxf(shi, 1e-24f)) * 127.0f;

    int rowlo = r0 + w * 16 + (l >> 2);
    #pragma unroll
    for (int f = 0; f < 16; f++) {
        int c0 = f * 8 + 2 * (l & 3);
        int q0 = __float2int_rn(acc[f][0] * rlo);
        int q1 = __float2int_rn(acc[f][1] * rlo);
        int q2 = __float2int_rn(acc[f][2] * rhi);
        int q3 = __float2int_rn(acc[f][3] * rhi);
        uint16_t plo = (uint16_t)((q0 & 0xff) | ((q1 & 0xff) << 8));
        uint16_t phi = (uint16_t)((q2 & 0xff) | ((q3 & 0xff) << 8));
        *reinterpret_cast<uint16_t*>(g_proj + (size_t)rowlo * DMEM + c0)       = plo;
        *reinterpret_cast<uint16_t*>(g_proj + (size_t)(rowlo + 8) * DMEM + c0) = phi;
    }
}

// ---------------------------------------------------------------------------
// Stage 2: upper-triangular sim tiles (jt >= it) via s8 IMMA (m16n8k32).
// 1024 CTAs x 8-9 tiles. 3 CTAs/SM (launch_bounds cap 84 regs): s8 hot
// loop needs ~60-70 live regs, so the cap should be spill-free and gives
// 24 warps/SM (+50% latency hiding vs the 2-CTA config).
// ---------------------------------------------------------------------------
__global__ void __launch_bounds__(256, 3) sim_kernel() {
    extern __shared__ unsigned char dsm[];
    uint32_t smA  = su32(dsm);
    uint32_t smB0 = smA + TILE8;
    uint32_t smB1 = smA + 2 * TILE8;

    int tid = threadIdx.x, wid = tid >> 5, l = tid & 31;
    int wm = wid >> 1, wn = wid & 1;

    int bid = blockIdx.x;
    int batch = bid >> 8;
    int p     = (bid >> 3) & 31;
    int q     = bid & 7;
    int n0    = NTILES - p;                 // tiles in row p
    int t0 = (q * 65) >> 3, t1 = ((q + 1) * 65) >> 3;

    const int8_t* pb = g_proj + (size_t)batch * NROWS * DMEM;
    int bi = batch * NROWS;                 // global row offset for this batch

    #define JOF(t) (((t) < n0) ? (p + (t)) : ((63 - p) + ((t) - n0)))
    #define IOF(t) (((t) < n0) ? p : (63 - p))

    int cur_i = IOF(t0);
    copy_tile8(smA, pb + (size_t)cur_i * 128 * DMEM, tid);
    copy_tile8(smB0, pb + (size_t)JOF(t0) * 128 * DMEM, tid);
    asm volatile("cp.async.commit_group;" ::: "memory");
    if (t0 + 1 < t1)
        copy_tile8(smB1, pb + (size_t)JOF(t0 + 1) * 128 * DMEM, tid);
    asm volatile("cp.async.commit_group;" ::: "memory");
    asm volatile("cp.async.wait_group 1;" ::: "memory");
    __syncthreads();

    uint32_t a[2][4][4];
    load_afrags8(a, smA, wm, l);

    for (int t = t0; t < t1; t++) {
        if (IOF(t) != cur_i) {             // row crossing (only 1-in-8 CTAs)
            cur_i = IOF(t);
            __syncthreads();
            copy_tile8(smA, pb + (size_t)cur_i * 128 * DMEM, tid);
            asm volatile("cp.async.commit_group;" ::: "memory");
            asm volatile("cp.async.wait_group 0;" ::: "memory");
            __syncthreads();
            load_afrags8(a, smA, wm, l);
        }
        int it = cur_i, jt = JOF(t);
        uint32_t smB = ((t - t0) & 1) ? smB1 : smB0;

        #pragma unroll 1
        for (int g = 0; g < 4; g++) {
            int n0c = wn * 64 + g * 16;
            int d[2][2][4];
            #pragma unroll
            for (int m = 0; m < 2; m++)
                #pragma unroll
                for (int h = 0; h < 2; h++)
                    #pragma unroll
                    for (int pp = 0; pp < 4; pp++) d[m][h][pp] = 0;

            #pragma unroll
            for (int k = 0; k < 4; k++) {
                int nn = n0c + (l & 7) + ((l & 16) ? 8 : 0);
                int chunk = k * 2 + ((l >> 3) & 1);
                uint32_t addr = smB + nn * 128 + ((chunk ^ (nn & 7)) << 4);
                uint32_t b0, b1, b2, b3;
                LDMATRIX_X4(b0, b1, b2, b3, addr);
                #pragma unroll
                for (int m = 0; m < 2; m++) {
                    MMA_S8(d[m][0], (uint32_t*)a[m][k], b0, b1);
                    MMA_S8(d[m][1], (uint32_t*)a[m][k], b2, b3);
                }
            }

            int vmax = d[0][0][0];
            #pragma unroll
            for (int m = 0; m < 2; m++)
                #pragma unroll
                for (int h = 0; h < 2; h++)
                    #pragma unroll
                    for (int pp = 0; pp < 4; pp++) vmax = max(vmax, d[m][h][pp]);
            unsigned warp_any = __ballot_sync(0xffffffffu, vmax > THRESHI);

            if (warp_any) {   // rare: diagonal tile self-sim, or a true hit
                bool diag = (it == jt);
                #pragma unroll
                for (int m = 0; m < 2; m++)
                    #pragma unroll
                    for (int h = 0; h < 2; h++)
                        #pragma unroll
                        for (int pp = 0; pp < 4; pp++) {
                            if (d[m][h][pp] > THRESHI) {
                                int ib = bi + it * 128 + wm * 32 + m * 16 + (l >> 2) + ((pp & 2) ? 8 : 0);
                                int jb = bi + jt * 128 + n0c + h * 8 + 2 * (l & 3) + (pp & 1);
                                if (ib != jb) {
                                    unsigned idx = atomicAdd(&g_hitcnt, diag ? 1u : 2u);
                                    if (idx < HITCAP)
                                        g_hits[idx] = make_uint2((unsigned)ib, (unsigned)jb);
                                    if (!diag && idx + 1 < HITCAP)
                                        g_hits[idx + 1] = make_uint2((unsigned)jb, (unsigned)ib);
                                }
                            }
                        }
            }
        }

        __syncthreads();
        if (t + 2 < t1)
            copy_tile8(smB, pb + (size_t)JOF(t + 2) * 128 * DMEM, tid);
        asm volatile("cp.async.commit_group;" ::: "memory");
        asm volatile("cp.async.wait_group 1;" ::: "memory");
        __syncthreads();
    }
    #undef JOF
    #undef IOF
}

// ---------------------------------------------------------------------------
// Stage 3 (merged hits+fin, measured 4.2us): per row, scan the (tiny) hit
// list; if this row has hits: out[row] = (X[row] + sum_j X[j]) / (1 + deg).
// Else untouched (out already holds X from proj).
// ---------------------------------------------------------------------------
__global__ void __launch_bounds__(256) fin_kernel(const float* __restrict__ X,
                                                  float* __restrict__ out) {
    unsigned row = blockIdx.x * 256 + threadIdx.x;
    unsigned nh = g_hitcnt;
    if (nh > HITCAP) nh = HITCAP;
    int deg = 0;
    for (unsigned h = 0; h < nh; h++)
        if (g_hits[h].x == row) deg++;
    if (deg > 0) {
        float inv = 1.0f / (1.0f + (float)deg);
        float* o = out + (size_t)row * DMEM;
        #pragma unroll 4
        for (int dcol = 0; dcol < DMEM; dcol++) {
            float acc = o[dcol];                      // == X[row][dcol]
            for (unsigned h = 0; h < nh; h++)
                if (g_hits[h].x == row)
                    acc += X[(size_t)g_hits[h].y * DMEM + dcol];
            o[dcol] = acc * inv;
        }
    }
}

// ---------------------------------------------------------------------------
extern "C" void kernel_launch(void* const* d_in, const int* in_sizes, int n_in,
                              void* d_out, int out_size) {
    (void)in_sizes; (void)n_in; (void)out_size;
    const float* X  = (const float*)d_in[0];
    const float* W  = (const float*)d_in[1];
    const float* Bv = (const float*)d_in[2];
    float* out = (float*)d_out;

    const int PROJ_SMEM = 2 * TILEB + 512;     // ~66 KB
    const int SIM_SMEM  = 3 * TILE8;           // 48 KB (3 CTAs/SM = 144 KB)
    cudaFuncSetAttribute(proj_kernel, cudaFuncAttributeMaxDynamicSharedMemorySize, PROJ_SMEM);
    cudaFuncSetAttribute(sim_kernel,  cudaFuncAttributeMaxDynamicSharedMemorySize, SIM_SMEM);

    proj_kernel<<<(NBATCH * NROWS) / 128, 256, PROJ_SMEM>>>(X, W, Bv, out);
    sim_kernel<<<NBATCH * 32 * 8, 256, SIM_SMEM>>>();
    fin_kernel<<<NBATCH * NROWS / 256, 256>>>(X, out);
}